// round 4
// baseline (speedup 1.0000x reference)
#include <cuda_runtime.h>
#include <cstdint>
#include <cstddef>

constexpr int B_ = 4, N_ = 2048, D_ = 64;
constexpr float GAMMA_ = 5.0f;
constexpr float TAU_F = 0.8f, TAU_C = 0.7f, TAU_P = 0.5f;

// ---------------------------------------------------------------------------
// Scratch (device globals -- allocation-free per harness rules)
// ---------------------------------------------------------------------------
__device__ float  g_nf[B_ * N_ * D_];   // normalized features
__device__ float4 g_f4[B_ * N_];        // normalized flow.xyz, 0
__device__ float4 g_p4[B_ * N_];        // pts.xyz, mask
__device__ float4 g_c4[B_ * N_];        // colors/255, label bits
__device__ float  g_rowA[B_ * N_];
__device__ float  g_neg[B_ * N_];
__device__ float  g_posfs[B_ * N_];
__device__ float  g_possum[B_ * N_];
__device__ float  g_rowSam[B_ * N_];
__device__ double g_pA[16], g_pV[16], g_pS[16];

using ull = unsigned long long;

__device__ __forceinline__ void fma2(ull& d, ull a, ull b) {
    asm("fma.rn.f32x2 %0, %1, %2, %0;" : "+l"(d) : "l"(a), "l"(b));
}
__device__ __forceinline__ float2 unpack2(ull v) {
    float2 r;
    asm("mov.b64 {%0, %1}, %2;" : "=f"(r.x), "=f"(r.y) : "l"(v));
    return r;
}

// ---------------------------------------------------------------------------
// Kernel 0: preprocess. One warp per point. Flow is pre-normalized
// (eps 1e-8 in the reference denominator shifts fsim by <=1e-4 worst case).
// ---------------------------------------------------------------------------
__global__ void k_pre(const float* __restrict__ feat,
                      const float* __restrict__ flow,
                      const float* __restrict__ pts,
                      const int*   __restrict__ cols,
                      const int*   __restrict__ sam,
                      const unsigned char* __restrict__ mask) {
    int p    = blockIdx.x * (blockDim.x >> 5) + (threadIdx.x >> 5);
    int lane = threadIdx.x & 31;
    if (p >= B_ * N_) return;

    const float2 v = ((const float2*)(feat + (size_t)p * D_))[lane];
    float s = v.x * v.x + v.y * v.y;
    #pragma unroll
    for (int o = 16; o; o >>= 1) s += __shfl_xor_sync(0xffffffffu, s, o);
    float inv = 1.0f / (sqrtf(s) + 1e-7f);
    ((float2*)(g_nf + (size_t)p * D_))[lane] = make_float2(v.x * inv, v.y * inv);

    if (lane == 0) {
        float fx = flow[p * 3], fy = flow[p * 3 + 1], fz = flow[p * 3 + 2];
        float fi = 1.0f / (sqrtf(fx * fx + fy * fy + fz * fz) + 1e-20f);
        g_f4[p] = make_float4(fx * fi, fy * fi, fz * fi, 0.0f);
        g_p4[p] = make_float4(pts[p * 3], pts[p * 3 + 1], pts[p * 3 + 2],
                              mask[p] ? 1.0f : 0.0f);
        g_c4[p] = make_float4(cols[p * 3]     * (1.0f / 255.0f),
                              cols[p * 3 + 1] * (1.0f / 255.0f),
                              cols[p * 3 + 2] * (1.0f / 255.0f),
                              __int_as_float(sam[p]));
    }
}

// ---------------------------------------------------------------------------
// Kernel 1: pair kernel, 4x4 register tiling, conflict-free operand layout.
//  Tiles stored as float2 s[k2][q][16] where point = 4*t + q. Each (k2,q)
//  row is exactly 128B: the 16 tx lanes' LDS.64 is one conflict-free phase;
//  ty is broadcast. Prefetch next tile into registers during compute.
// ---------------------------------------------------------------------------
__global__ void __launch_bounds__(256) k_pair() {
    const int b    = blockIdx.y;
    const int row0 = blockIdx.x * 64;
    const int tid  = threadIdx.x;
    const int tx   = tid & 15, ty = tid >> 4;

    __shared__ float2 sA[32][4][16];
    __shared__ float2 sB[32][4][16];
    __shared__ float4 sRF[64], sRP[64], sRC[64];
    __shared__ float4 sCF[64], sCP[64], sCC[64];

    const int bn0 = b * N_;
    const float4* nf4 = (const float4*)(g_nf + (size_t)b * N_ * D_);

    const int lm  = tid & 63;   // loader point-in-tile
    const int lk4 = tid >> 6;   // loader k4 base (stride 4 per iter)
    const int lq  = lm & 3, lt = lm >> 2;

    // ---- A tile (row block), loaded once ----
    #pragma unroll
    for (int l = 0; l < 4; l++) {
        int k4 = lk4 + 4 * l;
        float4 v = nf4[(size_t)(row0 + lm) * 16 + k4];
        sA[2 * k4][lq][lt]     = make_float2(v.x, v.y);
        sA[2 * k4 + 1][lq][lt] = make_float2(v.z, v.w);
    }
    if (tid < 64) {
        sRF[tid] = g_f4[bn0 + row0 + tid];
        sRP[tid] = g_p4[bn0 + row0 + tid];
        sRC[tid] = g_c4[bn0 + row0 + tid];
    }

    // ---- prefetch tile ct=0 ----
    float4 pv[4];
    #pragma unroll
    for (int l = 0; l < 4; l++)
        pv[l] = nf4[(size_t)lm * 16 + (lk4 + 4 * l)];
    float4 pF, pP, pC;
    if (tid < 64) { pF = g_f4[bn0 + tid]; pP = g_p4[bn0 + tid]; pC = g_c4[bn0 + tid]; }

    float acc[4][9];
    #pragma unroll
    for (int i = 0; i < 4; i++)
        #pragma unroll
        for (int q = 0; q < 9; q++) acc[i][q] = 0.f;

    for (int ct = 0; ct < N_; ct += 64) {
        // store prefetched tile
        #pragma unroll
        for (int l = 0; l < 4; l++) {
            int k4 = lk4 + 4 * l;
            sB[2 * k4][lq][lt]     = make_float2(pv[l].x, pv[l].y);
            sB[2 * k4 + 1][lq][lt] = make_float2(pv[l].z, pv[l].w);
        }
        if (tid < 64) { sCF[tid] = pF; sCP[tid] = pP; sCC[tid] = pC; }
        __syncthreads();

        // prefetch next tile while computing this one
        if (ct + 64 < N_) {
            #pragma unroll
            for (int l = 0; l < 4; l++)
                pv[l] = nf4[(size_t)(ct + 64 + lm) * 16 + (lk4 + 4 * l)];
            if (tid < 64) {
                pF = g_f4[bn0 + ct + 64 + tid];
                pP = g_p4[bn0 + ct + 64 + tid];
                pC = g_c4[bn0 + ct + 64 + tid];
            }
        }

        // ---- 4x4 dot via packed f32x2 FMA ----
        ull fs2[16];
        #pragma unroll
        for (int q = 0; q < 16; q++) fs2[q] = 0ULL;

        #pragma unroll
        for (int k2 = 0; k2 < 32; k2++) {
            ull av[4], bv[4];
            #pragma unroll
            for (int i = 0; i < 4; i++) av[i] = *(const ull*)&sA[k2][i][ty];
            #pragma unroll
            for (int j = 0; j < 4; j++) bv[j] = *(const ull*)&sB[k2][j][tx];
            #pragma unroll
            for (int i = 0; i < 4; i++)
                #pragma unroll
                for (int j = 0; j < 4; j++)
                    fma2(fs2[i * 4 + j], av[i], bv[j]);
        }

        // ---- epilogue ----
        #pragma unroll
        for (int j = 0; j < 4; j++) {
            const int mc = 4 * tx + j;
            const float4 fm = sCF[mc], pm = sCP[mc], cm = sCC[mc];
            const int labm = __float_as_int(cm.w);
            #pragma unroll
            for (int i = 0; i < 4; i++) {
                const int rr = 4 * ty + i;
                const float4 fr = sRF[rr], pr = sRP[rr], cr = sRC[rr];
                const float msk = pr.w * pm.w;
                float2 u = unpack2(fs2[i * 4 + j]);
                const float fs = u.x + u.y;

                float fsim = (fr.x * fm.x + fr.y * fm.y + fr.z * fm.z) * msk;
                float dx = cr.x - cm.x, dy = cr.y - cm.y, dz = cr.z - cm.z;
                float d2 = fmaxf(dx * dx + dy * dy + dz * dz, 1e-30f);
                float csim = (1.0f - d2 * rsqrtf(d2) * 0.57735026918962576f) * msk;
                dx = pr.x - pm.x; dy = pr.y - pm.y; dz = pr.z - pm.z;
                float e2 = fmaxf(dx * dx + dy * dy + dz * dz, 1e-30f);
                float psim = __expf(-50.0f * (e2 * rsqrtf(e2))) * msk;

                const float emfs = __expf(-fs);
                float a, gp, ep;
                a = __expf(GAMMA_ * (TAU_F - fsim));
                gp = __fdividef(1.0f, 1.0f + a);
                ep = __expf(fs * gp);
                acc[i][0] += ep; acc[i][1] = fmaf(emfs, ep, acc[i][1]);
                a = __expf(GAMMA_ * (TAU_C - csim));
                gp = __fdividef(1.0f, 1.0f + a);
                ep = __expf(fs * gp);
                acc[i][2] += ep; acc[i][3] = fmaf(emfs, ep, acc[i][3]);
                a = __expf(GAMMA_ * (TAU_P - psim));
                gp = __fdividef(1.0f, 1.0f + a);
                ep = __expf(fs * gp);
                acc[i][4] += ep; acc[i][5] = fmaf(emfs, ep, acc[i][5]);

                float efs = __expf(fs);
                int labr = __float_as_int(cr.w);
                float pos = (labr == labm) ? 1.0f : 0.0f;
                acc[i][6] = fmaf(efs, 1.0f - pos, acc[i][6]);
                acc[i][7] += pos;
                acc[i][8] = fmaf(fs, pos, acc[i][8]);
            }
        }
        __syncthreads();
    }

    // reduce across the 16 tx lanes (xor <=8 stays within the 16-lane group)
    #pragma unroll
    for (int i = 0; i < 4; i++)
        #pragma unroll
        for (int q = 0; q < 9; q++)
            #pragma unroll
            for (int o = 8; o; o >>= 1)
                acc[i][q] += __shfl_xor_sync(0xffffffffu, acc[i][q], o);

    if (tx == 0) {
        #pragma unroll
        for (int i = 0; i < 4; i++) {
            int bn = bn0 + row0 + 4 * ty + i;
            float lpp = __logf(1.0f + acc[i][0]) + __logf(1.0f + acc[i][1])
                      + __logf(1.0f + acc[i][2]) + __logf(1.0f + acc[i][3])
                      + __logf(1.0f + acc[i][4]) + __logf(1.0f + acc[i][5]);
            g_rowA[bn]   = lpp * sRP[4 * ty + i].w;
            g_neg[bn]    = acc[i][6];
            g_possum[bn] = acc[i][7];
            g_posfs[bn]  = acc[i][8];
        }
    }
}

// ---------------------------------------------------------------------------
// Kernel 2: SAM pass-2 -- recompute fs only for positive pairs (~32/row).
// ---------------------------------------------------------------------------
__global__ void __launch_bounds__(256) k_sam(const int* __restrict__ sam) {
    __shared__ float srow[8][64];
    const int w    = threadIdx.x >> 5;
    const int lane = threadIdx.x & 31;
    const int bn   = blockIdx.x * 8 + w;
    const int bBase = bn & ~(N_ - 1);
    const int labn = sam[bn];
    const float neg = g_neg[bn];

    if (lane < 16)
        ((float4*)srow[w])[lane] = ((const float4*)(g_nf + (size_t)bn * D_))[lane];
    __syncwarp();

    float acc = 0.f;
    for (int c = 0; c < 64; c++) {
        int m = c * 32 + lane;
        if (sam[bBase + m] == labn) {
            const float4* vp = (const float4*)(g_nf + (size_t)(bBase + m) * D_);
            float d = 0.f;
            #pragma unroll
            for (int q = 0; q < 16; q++) {
                float4 v = vp[q], aa = ((float4*)srow[w])[q];
                d = fmaf(aa.x, v.x, fmaf(aa.y, v.y, fmaf(aa.z, v.z, fmaf(aa.w, v.w, d))));
            }
            acc += __logf(__expf(d) + neg);
        }
    }
    #pragma unroll
    for (int o = 16; o; o >>= 1) acc += __shfl_xor_sync(0xffffffffu, acc, o);
    if (lane == 0)
        g_rowSam[bn] = (acc - g_posfs[bn]) / g_possum[bn];
}

// ---------------------------------------------------------------------------
// Kernel 3a: stage-1 reduction, 16 deterministic block partials.
//  Block bk covers elements [bk*512, bk*512+512) -- a single batch each.
// ---------------------------------------------------------------------------
__global__ void __launch_bounds__(512) k_f1(const unsigned char* __restrict__ mask) {
    const int i = blockIdx.x * 512 + threadIdx.x;
    double a = (double)g_rowA[i];
    double v = mask[i] ? 1.0 : 0.0;
    double s = (double)g_rowSam[i];
    #pragma unroll
    for (int o = 16; o; o >>= 1) {
        a += __shfl_xor_sync(0xffffffffu, a, o);
        v += __shfl_xor_sync(0xffffffffu, v, o);
        s += __shfl_xor_sync(0xffffffffu, s, o);
    }
    __shared__ double sh[3][16];
    const int w = threadIdx.x >> 5, lane = threadIdx.x & 31;
    if (lane == 0) { sh[0][w] = a; sh[1][w] = v; sh[2][w] = s; }
    __syncthreads();
    if (threadIdx.x < 16) {
        double x = sh[0][threadIdx.x];
        #pragma unroll
        for (int o = 8; o; o >>= 1) x += __shfl_xor_sync(0xffffu, x, o);
        if (threadIdx.x == 0) g_pA[blockIdx.x] = x;
    } else if (threadIdx.x < 48) {
        // nothing
    }
    if (threadIdx.x >= 32 && threadIdx.x < 48) {
        double x = sh[1][threadIdx.x - 32];
        #pragma unroll
        for (int o = 8; o; o >>= 1) x += __shfl_xor_sync(0xffff0000u, x, o);
        if (threadIdx.x == 32) g_pV[blockIdx.x] = x;
    }
    if (threadIdx.x >= 64 && threadIdx.x < 80) {
        double x = sh[2][threadIdx.x - 64];
        #pragma unroll
        for (int o = 8; o; o >>= 1) x += __shfl_xor_sync(0xffffu, x, o);
        if (threadIdx.x == 64) g_pS[blockIdx.x] = x;
    }
}

// ---------------------------------------------------------------------------
// Kernel 3b: combine 16 partials -> scalar.
// ---------------------------------------------------------------------------
__global__ void k_f2(float* __restrict__ out) {
    if (threadIdx.x == 0) {
        double A[4] = {0, 0, 0, 0}, V[4] = {0, 0, 0, 0}, S = 0.0;
        #pragma unroll
        for (int s = 0; s < 16; s++) {
            A[s >> 2] += g_pA[s];
            V[s >> 2] += g_pV[s];
            S         += g_pS[s];
        }
        double core = A[0] / V[0] + A[1] / V[1] + A[2] / V[2] + A[3] / V[3];
        out[0] = (float)(-core / (double)B_ + S / ((double)B_ * (double)N_));
    }
}

// ---------------------------------------------------------------------------
// Launcher
// ---------------------------------------------------------------------------
extern "C" void kernel_launch(void* const* d_in, const int* in_sizes, int n_in,
                              void* d_out, int out_size) {
    const float* feat = (const float*)d_in[0];
    const float* flow = (const float*)d_in[1];
    const float* pts  = (const float*)d_in[2];
    const int*   cols = (const int*)d_in[3];
    const int*   sam  = (const int*)d_in[4];
    const unsigned char* mask = (const unsigned char*)d_in[5];

    k_pre<<<(B_ * N_) / 8, 256>>>(feat, flow, pts, cols, sam, mask);
    dim3 g1(N_ / 64, B_);
    k_pair<<<g1, 256>>>();
    k_sam<<<(B_ * N_) / 8, 256>>>(sam);
    k_f1<<<16, 512>>>(mask);
    k_f2<<<1, 32>>>((float*)d_out);
}